// round 1
// baseline (speedup 1.0000x reference)
#include <cuda_runtime.h>

#define BB 2
#define KK 4
#define DD 128
#define HH 128
#define WW 128
#define NN (DD*HH*WW)          // 2097152
#define TY 8
#define TZ 16
#define REG_WT 0.0008

// ---------------- global scratch (no allocs allowed) ----------------
__device__ double g_Smem[BB*KK];
__device__ double g_Simg[BB*KK];
__device__ double g_J1;
__device__ double g_J2;

__global__ void zero_kernel() {
    int t = threadIdx.x;
    if (t < BB*KK) { g_Smem[t] = 0.0; g_Simg[t] = 0.0; }
    if (t == 0)    { g_J1 = 0.0; g_J2 = 0.0; }
}

__device__ __forceinline__ float warp_red(float v) {
    #pragma unroll
    for (int o = 16; o > 0; o >>= 1) v += __shfl_down_sync(0xffffffffu, v, o);
    return v;
}

// ---------------- pass 1: per-(b,k) sums of mem and img*mem ----------------
__global__ __launch_bounds__(256) void pass1_kernel(const float* __restrict__ yp,
                                                    const float* __restrict__ img) {
    const int ch = blockIdx.y;             // 0..7 = b*4+k
    const int b  = ch >> 2;
    const float4* __restrict__ p  = (const float4*)(yp  + (size_t)ch * NN);
    const float4* __restrict__ im = (const float4*)(img + (size_t)b  * NN);

    float sm = 0.f, si = 0.f;
    const int stride = gridDim.x * blockDim.x;
    for (int i = blockIdx.x * blockDim.x + threadIdx.x; i < NN/4; i += stride) {
        float4 pv = p[i];
        float4 iv = im[i];
        float m0 = pv.x*pv.x, m1 = pv.y*pv.y, m2 = pv.z*pv.z, m3 = pv.w*pv.w;
        sm += (m0 + m1) + (m2 + m3);
        si += m0*iv.x + m1*iv.y + m2*iv.z + m3*iv.w;
    }

    __shared__ float r1[8], r2[8];
    sm = warp_red(sm); si = warp_red(si);
    int lane = threadIdx.x & 31, w = threadIdx.x >> 5;
    if (lane == 0) { r1[w] = sm; r2[w] = si; }
    __syncthreads();
    if (w == 0) {
        float a = (lane < 8) ? r1[lane] : 0.f;
        float c = (lane < 8) ? r2[lane] : 0.f;
        a = warp_red(a); c = warp_red(c);
        if (lane == 0) {
            atomicAdd(&g_Smem[ch], (double)a);
            atomicAdd(&g_Simg[ch], (double)c);
        }
    }
}

// ---------------- pass 2: separable sliding-window stencil + J1/J2 reduce ----------------
// block = (128, 8) threads; tile = full x, TY rows, streams TZ z-planes.
__global__ __launch_bounds__(1024, 2) void pass2_kernel(const float* __restrict__ yp,
                                                        const float* __restrict__ img) {
    const int x  = threadIdx.x;            // 0..127
    const int ty = threadIdx.y;            // 0..7
    const int zc = blockIdx.x;             // 0..7
    const int yt = blockIdx.y;             // 0..15
    const int b  = blockIdx.z;             // 0..1
    const int y0 = yt * TY;
    const int z0 = zc * TZ;
    const int gy = y0 + ty;

    __shared__ float raw[KK][TY+2][132];   // x index shifted by +1; [0] and [129] are zero pad
    __shared__ float rx [KK][TY+2][128];   // 1D (x) 3-tap sums

    float v[KK];
    #pragma unroll
    for (int c = 0; c < KK; c++)
        v[c] = (float)(g_Simg[b*KK + c] / g_Smem[b*KK + c]);

    const float* __restrict__ imb = img + (size_t)b * NN;

    float s_zm1[KK], s_z[KK], s_zp1[KK], m_z[KK], m_zp1[KK];
    float accJ1 = 0.f, accJ2 = 0.f;

    // Load plane gz (as mem = p^2) into smem, build rx, extract s (2D 3x3 sum) and center mem.
    auto process_plane = [&](int gz, float* s_out, float* m_out) {
        __syncthreads();   // protect previous iteration's reads before overwriting
        const bool zok = (gz >= 0) && (gz < DD);
        #pragma unroll
        for (int c = 0; c < KK; c++) {
            const float* pc = yp + ((size_t)(b*KK + c)) * NN + (size_t)(zok ? gz : 0) * (HH*WW);
            {
                int yy = ty; int gyy = y0 + yy - 1;
                float val = (zok && gyy >= 0 && gyy < HH) ? pc[gyy*WW + x] : 0.f;
                raw[c][yy][x+1] = val * val;
                if (x == 0)   raw[c][yy][0]   = 0.f;
                if (x == 127) raw[c][yy][129] = 0.f;
            }
            if (ty < 2) {
                int yy = ty + 8; int gyy = y0 + yy - 1;
                float val = (zok && gyy >= 0 && gyy < HH) ? pc[gyy*WW + x] : 0.f;
                raw[c][yy][x+1] = val * val;
                if (x == 0)   raw[c][yy][0]   = 0.f;
                if (x == 127) raw[c][yy][129] = 0.f;
            }
        }
        __syncthreads();
        #pragma unroll
        for (int c = 0; c < KK; c++) {
            rx[c][ty][x] = raw[c][ty][x] + raw[c][ty][x+1] + raw[c][ty][x+2];
            if (ty < 2)
                rx[c][ty+8][x] = raw[c][ty+8][x] + raw[c][ty+8][x+1] + raw[c][ty+8][x+2];
        }
        __syncthreads();
        #pragma unroll
        for (int c = 0; c < KK; c++) {
            if (s_out) s_out[c] = rx[c][ty][x] + rx[c][ty+1][x] + rx[c][ty+2][x];
            if (m_out) m_out[c] = raw[c][ty+1][x+1];
        }
    };

    process_plane(z0 - 1, s_zm1, (float*)0);
    process_plane(z0,     s_z,   m_z);

    for (int z = z0; z < z0 + TZ; z++) {
        process_plane(z + 1, s_zp1, m_zp1);

        float iv = imb[(size_t)z * (HH*WW) + gy*WW + x];
        float Ms = 0.f, Tnb = 0.f, dotmn = 0.f, j1 = 0.f;
        #pragma unroll
        for (int c = 0; c < KK; c++) {
            float box = s_zm1[c] + s_z[c] + s_zp1[c];   // 3x3x3 sum incl. center
            float nb  = box - m_z[c];                   // zero-center kernel
            Ms    += m_z[c];
            Tnb   += nb;
            dotmn += m_z[c] * nb;
            float d = iv - v[c];
            j1 += m_z[c] * d * d;
        }
        accJ1 += j1;
        accJ2 += Tnb * Ms - dotmn;

        #pragma unroll
        for (int c = 0; c < KK; c++) {
            s_zm1[c] = s_z[c]; s_z[c] = s_zp1[c]; m_z[c] = m_zp1[c];
        }
    }

    // block reduce (1024 threads = 32 warps) -> 1 double atomic pair per block
    __shared__ float b1[32], b2[32];
    accJ1 = warp_red(accJ1); accJ2 = warp_red(accJ2);
    int tid  = ty * 128 + x;
    int lane = tid & 31, w = tid >> 5;
    if (lane == 0) { b1[w] = accJ1; b2[w] = accJ2; }
    __syncthreads();
    if (w == 0) {
        float a = b1[lane];
        float c = b2[lane];
        a = warp_red(a); c = warp_red(c);
        if (lane == 0) {
            atomicAdd(&g_J1, (double)a);
            atomicAdd(&g_J2, (double)c);
        }
    }
}

__global__ void fin_kernel(float* __restrict__ out) {
    double denom = (double)BB * (double)NN;
    out[0] = (float)(g_J1 / denom + REG_WT * (g_J2 / denom));
}

extern "C" void kernel_launch(void* const* d_in, const int* in_sizes, int n_in,
                              void* d_out, int out_size) {
    const float* yp  = (const float*)d_in[0];   // y_pred [2,4,128,128,128]
    const float* img = (const float*)d_in[1];   // image  [2,1,128,128,128]
    (void)in_sizes; (void)n_in; (void)out_size;

    zero_kernel<<<1, 32>>>();
    pass1_kernel<<<dim3(64, 8), 256>>>(yp, img);
    pass2_kernel<<<dim3(8, 16, 2), dim3(128, 8)>>>(yp, img);
    fin_kernel<<<1, 1>>>((float*)d_out);
}

// round 4
// speedup vs baseline: 1.6682x; 1.6682x over previous
#include <cuda_runtime.h>

#define BB 2
#define KK 4
#define DD 128
#define HH 128
#define WW 128
#define NN (DD*HH*WW)          // 2097152
#define TY 8
#define TZ 16
#define NBX 64                 // pass1 x-blocks
#define NBLK2 ((DD/TZ)*(HH/TY)*BB)   // 8*16*2 = 256 pass2 blocks
#define REG_WT 0.0008

// ---------------- global scratch (no allocs allowed) ----------------
__device__ float    g_p1[BB*KK][NBX];   // per-block partial sum(mem)
__device__ float    g_p2[BB*KK][NBX];   // per-block partial sum(img*mem)
__device__ double   g_J1, g_J2;
__device__ unsigned g_ticket;

__device__ __forceinline__ float warp_red(float v) {
    #pragma unroll
    for (int o = 16; o > 0; o >>= 1) v += __shfl_down_sync(0xffffffffu, v, o);
    return v;
}

// ---------------- pass 1: per-(b,k) sums of mem and img*mem (atomic-free) ----
__global__ __launch_bounds__(256) void pass1_kernel(const float* __restrict__ yp,
                                                    const float* __restrict__ img) {
    const int ch = blockIdx.y;             // 0..7 = b*4+k
    const int b  = ch >> 2;
    const float4* __restrict__ p  = (const float4*)(yp  + (size_t)ch * NN);
    const float4* __restrict__ im = (const float4*)(img + (size_t)b  * NN);

    float sm = 0.f, si = 0.f;
    const int stride = gridDim.x * blockDim.x;
    for (int i = blockIdx.x * blockDim.x + threadIdx.x; i < NN/4; i += stride) {
        float4 pv = p[i];
        float4 iv = im[i];
        float m0 = pv.x*pv.x, m1 = pv.y*pv.y, m2 = pv.z*pv.z, m3 = pv.w*pv.w;
        sm += (m0 + m1) + (m2 + m3);
        si += m0*iv.x + m1*iv.y + m2*iv.z + m3*iv.w;
    }

    __shared__ float r1[8], r2[8];
    sm = warp_red(sm); si = warp_red(si);
    int lane = threadIdx.x & 31, w = threadIdx.x >> 5;
    if (lane == 0) { r1[w] = sm; r2[w] = si; }
    __syncthreads();
    if (w == 0) {
        float a = (lane < 8) ? r1[lane] : 0.f;
        float c = (lane < 8) ? r2[lane] : 0.f;
        a = warp_red(a); c = warp_red(c);
        if (lane == 0) {
            g_p1[ch][blockIdx.x] = a;
            g_p2[ch][blockIdx.x] = c;
        }
    }
    if (blockIdx.x == 0 && blockIdx.y == 0 && threadIdx.x == 0) {
        g_J1 = 0.0; g_J2 = 0.0; g_ticket = 0u;
    }
}

// ---------------- pass 2: vectorized sliding-window stencil + full reduce ----
// block = (32, 8): warp w owns y-row y0+w (full x = 32 lanes x float4).
// One __syncthreads per plane via double-buffered raw planes.
__global__ __launch_bounds__(256) void pass2_kernel(const float* __restrict__ yp,
                                                    const float* __restrict__ img,
                                                    float* __restrict__ out) {
    const int lane = threadIdx.x;          // 0..31 -> x quad [4*lane, 4*lane+3]
    const int w    = threadIdx.y;          // 0..7 warp id == y row in tile
    const int zc = blockIdx.x;             // 0..7
    const int yt = blockIdx.y;             // 0..15
    const int b  = blockIdx.z;             // 0..1
    const int y0 = yt * TY;
    const int z0 = zc * TZ;

    __shared__ float4 raw[2][KK][TY+2][32];   // mem = p^2, double-buffered planes
    __shared__ float  vsh[KK];
    __shared__ float  s1[8], s2[8];

    // ---- centroids from pass1 partials: warp c reduces channel b*4+c ----
    if (w < KK) {
        int ch = b*KK + w;
        float sm = g_p1[ch][lane] + g_p1[ch][lane+32];
        float si = g_p2[ch][lane] + g_p2[ch][lane+32];
        sm = warp_red(sm); si = warp_red(si);
        if (lane == 0) vsh[w] = si / sm;
    }
    __syncthreads();
    float v0 = vsh[0], v1 = vsh[1], v2 = vsh[2], v3 = vsh[3];
    const float vreg[KK] = {v0, v1, v2, v3};

    const float* __restrict__ imb = img + (size_t)b * NN;

    // z-ring registers (per channel, float4 lanes):
    // sA = s_{pz-1}, sB = s_{pz-2} + s_{pz-1}, mP = center mem of plane pz-1
    float4 sA[KK], sB[KK], mP[KK];
    #pragma unroll
    for (int c = 0; c < KK; c++) {
        sA[c] = make_float4(0,0,0,0);
        sB[c] = make_float4(0,0,0,0);
        mP[c] = make_float4(0,0,0,0);
    }
    float4 aJ1 = make_float4(0,0,0,0), aJ2 = make_float4(0,0,0,0);

    for (int pz = z0 - 1; pz <= z0 + TZ; ++pz) {
        const int buf = pz & 1;
        const bool zok = (pz >= 0) && (pz < DD);

        // ---- load plane pz (as mem) into raw[buf]: 40 rows over 8 warps ----
        #pragma unroll
        for (int i = 0; i < 5; i++) {
            int r  = w + 8*i;              // 0..39
            int c  = r / 10;
            int yy = r - 10*c;
            int gyy = y0 + yy - 1;
            float4 val = make_float4(0,0,0,0);
            if (zok && gyy >= 0 && gyy < HH) {
                val = *(const float4*)(yp + ((size_t)(b*KK + c))*NN
                                          + (size_t)pz*(HH*WW) + (size_t)gyy*WW + 4*lane);
            }
            val.x *= val.x; val.y *= val.y; val.z *= val.z; val.w *= val.w;
            raw[buf][c][yy][lane] = val;
        }
        __syncthreads();

        // ---- emit prep ----
        const bool emit = (pz > z0);
        float4 iv = make_float4(0,0,0,0);
        if (emit) {
            iv = *(const float4*)(imb + (size_t)(pz-1)*(HH*WW) + (size_t)(y0+w)*WW + 4*lane);
        }
        float4 Ms = make_float4(0,0,0,0), Tnb = make_float4(0,0,0,0);
        float4 dmn = make_float4(0,0,0,0), j1 = make_float4(0,0,0,0);

        #pragma unroll
        for (int c = 0; c < KK; c++) {
            // vertical 3-tap from smem (aligned float4 reads)
            float4 r0 = raw[buf][c][w  ][lane];
            float4 r1 = raw[buf][c][w+1][lane];
            float4 r2 = raw[buf][c][w+2][lane];
            float4 ry;
            ry.x = r0.x + r1.x + r2.x;
            ry.y = r0.y + r1.y + r2.y;
            ry.z = r0.z + r1.z + r2.z;
            ry.w = r0.w + r1.w + r2.w;
            // horizontal 3-tap via shuffles (warp spans full x-row)
            float lf = __shfl_up_sync  (0xffffffffu, ry.w, 1);
            float rt = __shfl_down_sync(0xffffffffu, ry.x, 1);
            lf = (lane == 0)  ? 0.f : lf;
            rt = (lane == 31) ? 0.f : rt;
            float4 s;                       // 2D 3x3 sum at plane pz
            s.x = lf   + ry.x + ry.y;
            s.y = ry.x + ry.y + ry.z;
            s.z = ry.y + ry.z + ry.w;
            s.w = ry.z + ry.w + rt;

            if (emit) {
                float4 m = mP[c];
                float4 box, nb;
                box.x = sB[c].x + s.x;  box.y = sB[c].y + s.y;
                box.z = sB[c].z + s.z;  box.w = sB[c].w + s.w;
                nb.x = box.x - m.x; nb.y = box.y - m.y;
                nb.z = box.z - m.z; nb.w = box.w - m.w;
                Ms.x += m.x; Ms.y += m.y; Ms.z += m.z; Ms.w += m.w;
                Tnb.x += nb.x; Tnb.y += nb.y; Tnb.z += nb.z; Tnb.w += nb.w;
                dmn.x += m.x*nb.x; dmn.y += m.y*nb.y;
                dmn.z += m.z*nb.z; dmn.w += m.w*nb.w;
                float vc = vreg[c];
                float dx = iv.x - vc, dy = iv.y - vc, dz = iv.z - vc, dw = iv.w - vc;
                j1.x += m.x*dx*dx; j1.y += m.y*dy*dy;
                j1.z += m.z*dz*dz; j1.w += m.w*dw*dw;
            }
            // ring update
            sB[c].x = sA[c].x + s.x; sB[c].y = sA[c].y + s.y;
            sB[c].z = sA[c].z + s.z; sB[c].w = sA[c].w + s.w;
            sA[c] = s;
            mP[c] = r1;
        }
        if (emit) {
            aJ1.x += j1.x; aJ1.y += j1.y; aJ1.z += j1.z; aJ1.w += j1.w;
            aJ2.x += Tnb.x*Ms.x - dmn.x;
            aJ2.y += Tnb.y*Ms.y - dmn.y;
            aJ2.z += Tnb.z*Ms.z - dmn.z;
            aJ2.w += Tnb.w*Ms.w - dmn.w;
        }
    }

    // ---- block reduce (8 warps) -> 1 double atomic pair per block ----
    float a1 = (aJ1.x + aJ1.y) + (aJ1.z + aJ1.w);
    float a2 = (aJ2.x + aJ2.y) + (aJ2.z + aJ2.w);
    a1 = warp_red(a1); a2 = warp_red(a2);
    if (lane == 0) { s1[w] = a1; s2[w] = a2; }
    __syncthreads();
    if (w == 0) {
        float b1 = (lane < 8) ? s1[lane] : 0.f;
        float b2 = (lane < 8) ? s2[lane] : 0.f;
        b1 = warp_red(b1); b2 = warp_red(b2);
        if (lane == 0) {
            atomicAdd(&g_J1, (double)b1);
            atomicAdd(&g_J2, (double)b2);
            __threadfence();
            unsigned t = atomicAdd(&g_ticket, 1u);
            if (t == NBLK2 - 1) {
                double j1s = atomicAdd(&g_J1, 0.0);
                double j2s = atomicAdd(&g_J2, 0.0);
                double denom = (double)BB * (double)NN;
                out[0] = (float)(j1s / denom + REG_WT * (j2s / denom));
            }
        }
    }
}

extern "C" void kernel_launch(void* const* d_in, const int* in_sizes, int n_in,
                              void* d_out, int out_size) {
    const float* yp  = (const float*)d_in[0];   // y_pred [2,4,128,128,128]
    const float* img = (const float*)d_in[1];   // image  [2,1,128,128,128]
    (void)in_sizes; (void)n_in; (void)out_size;

    pass1_kernel<<<dim3(NBX, BB*KK), 256>>>(yp, img);
    pass2_kernel<<<dim3(DD/TZ, HH/TY, BB), dim3(32, TY)>>>(yp, img, (float*)d_out);
}

// round 7
// speedup vs baseline: 2.4728x; 1.4824x over previous
#include <cuda_runtime.h>

#define BB 2
#define KK 4
#define DD 128
#define HH 128
#define WW 128
#define NN (DD*HH*WW)          // 2097152
#define TY 8
#define TZ 16
#define NBX 64                 // pass1 x-blocks
#define NBLK2 ((DD/TZ)*(HH/TY)*BB)   // 8*16*2 = 256 pass2 blocks
#define REG_WT 0.0008

// ---------------- global scratch (no allocs allowed) ----------------
__device__ float    g_p1[BB*KK][NBX];   // per-block partial sum(mem)
__device__ float    g_p2[BB*KK][NBX];   // per-block partial sum(img*mem)
__device__ double   g_J1, g_J2;
__device__ unsigned g_ticket;

__device__ __forceinline__ float warp_red(float v) {
    #pragma unroll
    for (int o = 16; o > 0; o >>= 1) v += __shfl_down_sync(0xffffffffu, v, o);
    return v;
}

// ---------------- pass 1: per-(b,k) sums of mem and img*mem (atomic-free) ----
__global__ __launch_bounds__(256) void pass1_kernel(const float* __restrict__ yp,
                                                    const float* __restrict__ img) {
    const int ch = blockIdx.y;             // 0..7 = b*4+k
    const int b  = ch >> 2;
    const float4* __restrict__ p  = (const float4*)(yp  + (size_t)ch * NN);
    const float4* __restrict__ im = (const float4*)(img + (size_t)b  * NN);

    float sm = 0.f, si = 0.f;
    const int stride = gridDim.x * blockDim.x;
    for (int i = blockIdx.x * blockDim.x + threadIdx.x; i < NN/4; i += stride) {
        float4 pv = p[i];
        float4 iv = im[i];
        float m0 = pv.x*pv.x, m1 = pv.y*pv.y, m2 = pv.z*pv.z, m3 = pv.w*pv.w;
        sm += (m0 + m1) + (m2 + m3);
        si += m0*iv.x + m1*iv.y + m2*iv.z + m3*iv.w;
    }

    __shared__ float r1[8], r2[8];
    sm = warp_red(sm); si = warp_red(si);
    int lane = threadIdx.x & 31, w = threadIdx.x >> 5;
    if (lane == 0) { r1[w] = sm; r2[w] = si; }
    __syncthreads();
    if (w == 0) {
        float a = (lane < 8) ? r1[lane] : 0.f;
        float c = (lane < 8) ? r2[lane] : 0.f;
        a = warp_red(a); c = warp_red(c);
        if (lane == 0) {
            g_p1[ch][blockIdx.x] = a;
            g_p2[ch][blockIdx.x] = c;
        }
    }
    if (blockIdx.x == 0 && blockIdx.y == 0 && threadIdx.x == 0) {
        g_J1 = 0.0; g_J2 = 0.0; g_ticket = 0u;
    }
}

// ---------------- pass 2: cp.async-pipelined sliding-window stencil --------
// block = (32, 8): warp w owns y-row y0+w (full x = 32 lanes x float4).
// Plane pz+1 streams in via cp.async while plane pz is computed from smem.
__global__ __launch_bounds__(256, 2) void pass2_kernel(const float* __restrict__ yp,
                                                       const float* __restrict__ img,
                                                       float* __restrict__ out) {
    const int lane = threadIdx.x;          // 0..31 -> x quad [4*lane, 4*lane+3]
    const int w    = threadIdx.y;          // 0..7 warp id == y row in tile
    const int zc = blockIdx.x;             // 0..7
    const int yt = blockIdx.y;             // 0..15
    const int b  = blockIdx.z;             // 0..1
    const int y0 = yt * TY;
    const int z0 = zc * TZ;

    __shared__ float4 raw[2][KK][TY+2][32];   // RAW p values (squared on read)
    __shared__ float  vsh[KK];
    __shared__ float  s1[8], s2[8];

    // ---- centroids from pass1 partials: warp c reduces channel b*4+c ----
    if (w < KK) {
        int ch = b*KK + w;
        float sm = g_p1[ch][lane] + g_p1[ch][lane+32];
        float si = g_p2[ch][lane] + g_p2[ch][lane+32];
        sm = warp_red(sm); si = warp_red(si);
        if (lane == 0) vsh[w] = si / sm;
    }
    __syncthreads();
    const float vreg[KK] = {vsh[0], vsh[1], vsh[2], vsh[3]};

    const float* __restrict__ imb = img + (size_t)b * NN;

    // issue cp.async loads for plane pz into raw[pz&1] (40 rows over 8 warps)
    auto issue_plane = [&](int pz) {
        const int buf = pz & 1;
        const bool zok = (pz >= 0) && (pz < DD);
        #pragma unroll
        for (int i = 0; i < 5; i++) {
            int r  = w + 8*i;              // 0..39
            int c  = r / 10;
            int yy = r - 10*c;
            int gyy = y0 + yy - 1;
            bool ok = zok && (gyy >= 0) && (gyy < HH);
            const float* src = yp + ((size_t)(b*KK + c))*NN
                                  + (size_t)(ok ? pz : 0)*(HH*WW)
                                  + (size_t)(ok ? gyy : 0)*WW + 4*lane;
            unsigned dst = (unsigned)__cvta_generic_to_shared(&raw[buf][c][yy][lane]);
            int sz = ok ? 16 : 0;          // src-size 0 -> zero-fill
            asm volatile("cp.async.cg.shared.global [%0], [%1], 16, %2;\n"
                         :: "r"(dst), "l"(src), "r"(sz));
        }
        asm volatile("cp.async.commit_group;\n");
    };

    // z-ring registers (per channel, float4 lanes):
    // sA = s_{pz-1}, sB = s_{pz-2}+s_{pz-1}, mP = center mem of plane pz-1
    float4 sA[KK], sB[KK], mP[KK];
    #pragma unroll
    for (int c = 0; c < KK; c++) {
        sA[c] = make_float4(0,0,0,0);
        sB[c] = make_float4(0,0,0,0);
        mP[c] = make_float4(0,0,0,0);
    }
    float4 aJ1 = make_float4(0,0,0,0), aJ2 = make_float4(0,0,0,0);

    issue_plane(z0 - 1);

    for (int pz = z0 - 1; pz <= z0 + TZ; ++pz) {
        const int buf = pz & 1;

        asm volatile("cp.async.wait_group 0;\n" ::: "memory");
        __syncthreads();                      // plane pz resident; prior reads done
        if (pz < z0 + TZ) issue_plane(pz + 1); // overlap with compute below

        const bool emit = (pz > z0);
        float4 iv = make_float4(0,0,0,0);
        if (emit) {
            iv = *(const float4*)(imb + (size_t)(pz-1)*(HH*WW) + (size_t)(y0+w)*WW + 4*lane);
        }
        float4 Ms = make_float4(0,0,0,0), Tnb = make_float4(0,0,0,0);
        float4 dmn = make_float4(0,0,0,0), j1 = make_float4(0,0,0,0);

        #pragma unroll
        for (int c = 0; c < KK; c++) {
            // vertical 3-tap from smem (square on read: mem = p^2)
            float4 r0 = raw[buf][c][w  ][lane];
            float4 r1 = raw[buf][c][w+1][lane];
            float4 r2 = raw[buf][c][w+2][lane];
            r0.x *= r0.x; r0.y *= r0.y; r0.z *= r0.z; r0.w *= r0.w;
            r1.x *= r1.x; r1.y *= r1.y; r1.z *= r1.z; r1.w *= r1.w;
            r2.x *= r2.x; r2.y *= r2.y; r2.z *= r2.z; r2.w *= r2.w;
            float4 ry;
            ry.x = r0.x + r1.x + r2.x;
            ry.y = r0.y + r1.y + r2.y;
            ry.z = r0.z + r1.z + r2.z;
            ry.w = r0.w + r1.w + r2.w;
            // horizontal 3-tap via shuffles (warp spans full x-row)
            float lf = __shfl_up_sync  (0xffffffffu, ry.w, 1);
            float rt = __shfl_down_sync(0xffffffffu, ry.x, 1);
            lf = (lane == 0)  ? 0.f : lf;
            rt = (lane == 31) ? 0.f : rt;
            float4 s;                       // 2D 3x3 sum at plane pz
            s.x = lf   + ry.x + ry.y;
            s.y = ry.x + ry.y + ry.z;
            s.z = ry.y + ry.z + ry.w;
            s.w = ry.z + ry.w + rt;

            if (emit) {
                float4 m = mP[c];
                float4 box, nb;
                box.x = sB[c].x + s.x;  box.y = sB[c].y + s.y;
                box.z = sB[c].z + s.z;  box.w = sB[c].w + s.w;
                nb.x = box.x - m.x; nb.y = box.y - m.y;
                nb.z = box.z - m.z; nb.w = box.w - m.w;
                Ms.x += m.x; Ms.y += m.y; Ms.z += m.z; Ms.w += m.w;
                Tnb.x += nb.x; Tnb.y += nb.y; Tnb.z += nb.z; Tnb.w += nb.w;
                dmn.x += m.x*nb.x; dmn.y += m.y*nb.y;
                dmn.z += m.z*nb.z; dmn.w += m.w*nb.w;
                float vc = vreg[c];
                float dx = iv.x - vc, dy = iv.y - vc, dz = iv.z - vc, dw = iv.w - vc;
                j1.x += m.x*dx*dx; j1.y += m.y*dy*dy;
                j1.z += m.z*dz*dz; j1.w += m.w*dw*dw;
            }
            // ring update
            sB[c].x = sA[c].x + s.x; sB[c].y = sA[c].y + s.y;
            sB[c].z = sA[c].z + s.z; sB[c].w = sA[c].w + s.w;
            sA[c] = s;
            mP[c] = r1;
        }
        if (emit) {
            aJ1.x += j1.x; aJ1.y += j1.y; aJ1.z += j1.z; aJ1.w += j1.w;
            aJ2.x += Tnb.x*Ms.x - dmn.x;
            aJ2.y += Tnb.y*Ms.y - dmn.y;
            aJ2.z += Tnb.z*Ms.z - dmn.z;
            aJ2.w += Tnb.w*Ms.w - dmn.w;
        }
    }

    // ---- block reduce (8 warps) -> 1 double atomic pair per block ----
    float a1 = (aJ1.x + aJ1.y) + (aJ1.z + aJ1.w);
    float a2 = (aJ2.x + aJ2.y) + (aJ2.z + aJ2.w);
    a1 = warp_red(a1); a2 = warp_red(a2);
    if (lane == 0) { s1[w] = a1; s2[w] = a2; }
    __syncthreads();
    if (w == 0) {
        float b1 = (lane < 8) ? s1[lane] : 0.f;
        float b2 = (lane < 8) ? s2[lane] : 0.f;
        b1 = warp_red(b1); b2 = warp_red(b2);
        if (lane == 0) {
            atomicAdd(&g_J1, (double)b1);
            atomicAdd(&g_J2, (double)b2);
            __threadfence();
            unsigned t = atomicAdd(&g_ticket, 1u);
            if (t == NBLK2 - 1) {
                double j1s = atomicAdd(&g_J1, 0.0);
                double j2s = atomicAdd(&g_J2, 0.0);
                double denom = (double)BB * (double)NN;
                out[0] = (float)(j1s / denom + REG_WT * (j2s / denom));
            }
        }
    }
}

extern "C" void kernel_launch(void* const* d_in, const int* in_sizes, int n_in,
                              void* d_out, int out_size) {
    const float* yp  = (const float*)d_in[0];   // y_pred [2,4,128,128,128]
    const float* img = (const float*)d_in[1];   // image  [2,1,128,128,128]
    (void)in_sizes; (void)n_in; (void)out_size;

    pass1_kernel<<<dim3(NBX, BB*KK), 256>>>(yp, img);
    pass2_kernel<<<dim3(DD/TZ, HH/TY, BB), dim3(32, TY)>>>(yp, img, (float*)d_out);
}